// round 4
// baseline (speedup 1.0000x reference)
#include <cuda_runtime.h>

// CRF NLL, prob-domain forward with chunked renormalization.
// B=64, S=512, T=64 (62 tags + START=62 + END=63).
// R4: 2 batches per 256-thread CTA, computed by the SAME threads in one
//     barrier interval (ILP pairing fills the latency tail). Plain
//     __syncthreads, grid=32.
//
// Inputs: d_in[0] feats f32 [B,S,T], d_in[1] transitions f32 [T,T],
//         d_in[2] mask i32 [B,S] (contiguous prefix), d_in[3] tags i32 [B,S]
// Output: f32 scalar sum_b (forward_b - gold_b)

#define B_    64
#define S_    512
#define T_    64
#define CHUNK 8
#define NB    2      // batches per CTA (ILP-paired)

__device__ float g_res[B_];

__global__ __launch_bounds__(256, 1) void crf_forward_kernel(
    const float* __restrict__ feats,
    const float* __restrict__ trans,
    const int*   __restrict__ mask,
    const int*   __restrict__ tags)
{
    __shared__ float trans_sh[T_ * T_];
    __shared__ float p_sh[NB][2][T_];
    __shared__ float f_sh[NB][CHUNK][T_];
    __shared__ int   tags_sh[NB][S_];
    __shared__ float redg[NB][8];
    __shared__ float redf[NB][2];
    __shared__ int   redi[NB][8];

    const int tid  = threadIdx.x;
    const int lane = tid & 31;
    const int warp = tid >> 5;
    const int seg  = lane >> 3;                 // 0..3 : i-segment of 16
    const int j    = (warp << 3) | (lane & 7);  // 0..63 : state column
    const int r    = tid >> 6;                  // 0..3 : staging row group
    const int col  = tid & 63;                  // staging column

    const int b0 = blockIdx.x * NB;

    const float* fb[NB];
    #pragma unroll
    for (int g = 0; g < NB; ++g) fb[g] = feats + (size_t)(b0 + g) * S_ * T_;

    // ---- stage transitions (coalesced float4) ----
    {
        const float4* t4 = (const float4*)trans;
        float4*       s4 = (float4*)trans_sh;
        #pragma unroll
        for (int i = 0; i < 4; ++i) s4[i * 256 + tid] = t4[i * 256 + tid];
    }
    // ---- tags + lengths (both batches) ----
    #pragma unroll
    for (int g = 0; g < NB; ++g) {
        const int* maskb = mask + (b0 + g) * S_;
        const int* tagsb = tags + (b0 + g) * S_;
        int lenp = 0;
        #pragma unroll
        for (int k = 0; k < 2; ++k) {
            tags_sh[g][k * 256 + tid] = tagsb[k * 256 + tid];
            lenp += maskb[k * 256 + tid];
        }
        #pragma unroll
        for (int o = 16; o; o >>= 1) lenp += __shfl_xor_sync(0xffffffffu, lenp, o);
        if (lane == 0) redi[g][warp] = lenp;
    }
    __syncthreads();
    int len[NB];
    #pragma unroll
    for (int g = 0; g < NB; ++g) {
        int l = 0;
        #pragma unroll
        for (int w = 0; w < 8; ++w) l += redi[g][w];
        len[g] = l;
    }
    const int lenmax = max(len[0], len[1]);

    // ---- gold path scores ----
    #pragma unroll
    for (int g = 0; g < NB; ++g) {
        float gs = 0.f;
        #pragma unroll
        for (int kk = 0; kk < 2; ++kk) {
            int s = kk * 256 + tid;
            if (s < len[g]) {
                int tg = tags_sh[g][s];
                int pv = s ? tags_sh[g][s - 1] : (T_ - 2);
                gs += fb[g][s * T_ + tg] + trans_sh[pv * T_ + tg];
            }
        }
        if (tid == 0) gs += trans_sh[tags_sh[g][len[g] - 1] * T_ + (T_ - 1)];
        #pragma unroll
        for (int o = 16; o; o >>= 1) gs += __shfl_xor_sync(0xffffffffu, gs, o);
        if (lane == 0) redg[g][warp] = gs;
    }

    // ---- E segment into registers (shared across both batches) ----
    float e[16];
    #pragma unroll
    for (int rr = 0; rr < 16; ++rr)
        e[rr] = __expf(trans_sh[(seg * 16 + rr) * T_ + j]);

    // ---- init p_0 for both batches (threads 0..127) ----
    if (tid < 2 * T_) {
        int g = tid >> 6, jj = tid & 63;
        p_sh[g][0][jj] = __expf(fb[g][jj] + trans_sh[(T_ - 2) * T_ + jj]);
    }

    // ---- prefetch first chunk feats ----
    int c = 1;
    float fr[NB][2];
    #pragma unroll
    for (int g = 0; g < NB; ++g) {
        int r0 = min(c + r,     S_ - 1);
        int r1 = min(c + r + 4, S_ - 1);
        fr[g][0] = fb[g][r0 * T_ + col];
        fr[g][1] = fb[g][r1 * T_ + col];
    }
    __syncthreads();

    // ---- forward recurrence (both batches per barrier interval) ----
    int   cur = 0;
    float logacc[NB] = {0.f, 0.f};

    while (c < lenmax) {
        // stage exp(f) for this chunk
        #pragma unroll
        for (int g = 0; g < NB; ++g) {
            f_sh[g][r][col]     = __expf(fr[g][0]);
            f_sh[g][r + 4][col] = __expf(fr[g][1]);
        }
        // prefetch next chunk
        int nc = c + CHUNK;
        if (nc < S_) {
            #pragma unroll
            for (int g = 0; g < NB; ++g) {
                int r0 = min(nc + r,     S_ - 1);
                int r1 = min(nc + r + 4, S_ - 1);
                fr[g][0] = fb[g][r0 * T_ + col];
                fr[g][1] = fb[g][r1 * T_ + col];
            }
        }

        // renormalize both batches: z_g = sum(p_g)
        float scale[NB];
        #pragma unroll
        for (int g = 0; g < NB; ++g) {
            const float4* pv4 = (const float4*)p_sh[g][cur];
            float z0 = 0.f, z1 = 0.f, z2 = 0.f, z3 = 0.f;
            #pragma unroll
            for (int i = 0; i < 16; i += 4) {
                float4 q0 = pv4[i],     q1 = pv4[i + 1];
                float4 q2 = pv4[i + 2], q3 = pv4[i + 3];
                z0 += (q0.x + q0.y) + (q0.z + q0.w);
                z1 += (q1.x + q1.y) + (q1.z + q1.w);
                z2 += (q2.x + q2.y) + (q2.z + q2.w);
                z3 += (q3.x + q3.y) + (q3.z + q3.w);
            }
            float z = (z0 + z1) + (z2 + z3);
            scale[g] = __fdividef(1.0f, z);
            logacc[g] += __logf(z);
        }

        const int cnt = min(CHUNK, lenmax - c);
        __syncthreads();   // f_sh visible; all p reads done

        #pragma unroll
        for (int k = 0; k < CHUNK; ++k) {
            if (k >= cnt) break;   // uniform
            // early, off-critical-path loads
            float fk0 = f_sh[0][k][j];
            float fk1 = f_sh[1][k][j];
            float pj0 = p_sh[0][cur][j];
            float pj1 = p_sh[1][cur][j];
            const float4* pa = (const float4*)(p_sh[0][cur] + (seg << 4));
            const float4* pb = (const float4*)(p_sh[1][cur] + (seg << 4));
            float a0 = 0.f, a1 = 0.f, a2 = 0.f, a3 = 0.f;
            float b0a = 0.f, b1a = 0.f, b2a = 0.f, b3a = 0.f;
            #pragma unroll
            for (int i = 0; i < 4; ++i) {
                float4 qa = pa[i];
                float4 qb = pb[i];
                a0  = fmaf(qa.x, e[4 * i + 0], a0);
                b0a = fmaf(qb.x, e[4 * i + 0], b0a);
                a1  = fmaf(qa.y, e[4 * i + 1], a1);
                b1a = fmaf(qb.y, e[4 * i + 1], b1a);
                a2  = fmaf(qa.z, e[4 * i + 2], a2);
                b2a = fmaf(qb.z, e[4 * i + 2], b2a);
                a3  = fmaf(qa.w, e[4 * i + 3], a3);
                b3a = fmaf(qb.w, e[4 * i + 3], b3a);
            }
            float va = (a0 + a1) + (a2 + a3);
            float vb = (b0a + b1a) + (b2a + b3a);
            va += __shfl_xor_sync(0xffffffffu, va, 8);
            vb += __shfl_xor_sync(0xffffffffu, vb, 8);
            va += __shfl_xor_sync(0xffffffffu, va, 16);
            vb += __shfl_xor_sync(0xffffffffu, vb, 16);
            // freeze past each batch's length (mask semantics)
            float q0 = ((c + k) < len[0]) ? va * fk0 : pj0;
            float q1 = ((c + k) < len[1]) ? vb * fk1 : pj1;
            if (k == 0) { q0 *= scale[0]; q1 *= scale[1]; }
            if (seg == 0) {
                p_sh[0][cur ^ 1][j] = q0;
                p_sh[1][cur ^ 1][j] = q1;
            }
            __syncthreads();
            cur ^= 1;
        }
        c += CHUNK;
    }

    // ---- final transition into END (both batches) ----
    if (tid < 2 * T_) {
        int g = tid >> 6, jj = tid & 63;
        float v = p_sh[g][cur][jj] * __expf(trans_sh[jj * T_ + (T_ - 1)]);
        #pragma unroll
        for (int o = 16; o; o >>= 1) v += __shfl_xor_sync(0xffffffffu, v, o);
        if ((jj & 31) == 0) redf[g][(jj >> 5)] = v;
    }
    __syncthreads();
    if (tid < NB) {
        int g = tid;
        float forward = logacc[g] + __logf(redf[g][0] + redf[g][1]);
        float gold = 0.f;
        #pragma unroll
        for (int w = 0; w < 8; ++w) gold += redg[g][w];
        g_res[b0 + g] = forward - gold;
    }
}

__global__ void crf_reduce_kernel(float* __restrict__ out)
{
    const int tid  = threadIdx.x;
    const int lane = tid & 31;
    const int warp = tid >> 5;
    __shared__ float sh[2];

    float v = g_res[tid];
    #pragma unroll
    for (int o = 16; o; o >>= 1) v += __shfl_xor_sync(0xffffffffu, v, o);
    if (lane == 0) sh[warp] = v;
    __syncthreads();
    if (tid == 0) out[0] = sh[0] + sh[1];
}

extern "C" void kernel_launch(void* const* d_in, const int* in_sizes, int n_in,
                              void* d_out, int out_size)
{
    const float* feats = (const float*)d_in[0];
    const float* trans = (const float*)d_in[1];
    const int*   mask  = (const int*)d_in[2];
    const int*   tags  = (const int*)d_in[3];
    float* out = (float*)d_out;

    crf_forward_kernel<<<B_ / NB, 256>>>(feats, trans, mask, tags);
    crf_reduce_kernel<<<1, 64>>>(out);
}